// round 7
// baseline (speedup 1.0000x reference)
#include <cuda_runtime.h>
#include <cuda_bf16.h>
#include <math.h>
#include <stdint.h>

#define E_N   4096
#define H_N   512
#define NH_N  4
#define HD_N  128
#define FFN_N 1024
#define H3_N  1536

// ---------------- fp32 scratch ----------------
__device__ float g_msg [E_N * H_N];
__device__ float g_agg [E_N * H_N];
__device__ float g_gi  [E_N * H3_N];
__device__ float g_gh  [E_N * H3_N];
__device__ float g_h   [E_N * H_N];
__device__ float g_qkv [E_N * H3_N];
__device__ float g_yprj[E_N * H_N];
__device__ float g_f   [E_N * FFN_N];
__device__ int   g_idx64_flag;

// ---------------- packed bf16x2 hi/lo planes ----------------
// activations: [rows][K/2] words
__device__ uint32_t g_xhi   [E_N * 256], g_xlo   [E_N * 256];
__device__ uint32_t g_agghi [E_N * 256], g_agglo [E_N * 256];
__device__ uint32_t g_hhi   [E_N * 256], g_hlo   [E_N * 256];
__device__ uint32_t g_attnhi[E_N * 256], g_attnlo[E_N * 256];
__device__ uint32_t g_ynhi  [E_N * 256], g_ynlo  [E_N * 256];
__device__ uint32_t g_gacthi[E_N * 256], g_gactlo[E_N * 256];
// weights combined: cumulative word offsets (pairs):
// W_msg 512x256, W_ih 1536x256, W_hh 1536x256, W_inp 1536x256,
// W_outp 512x256, W_lin 512x256, W_f1 1024x256
#define WOFF_MSG  0
#define WOFF_IH   131072
#define WOFF_HH   524288
#define WOFF_INP  917504
#define WOFF_OUTP 1310720
#define WOFF_LIN  1441792
#define WOFF_F1   1572864
#define WTOTAL    1835008
__device__ uint32_t g_whi[WTOTAL], g_wlo[WTOTAL];
// attention Q/K per-head planes [NH][E][HD/2]; VT [NH][HD][E/2]
__device__ uint32_t g_qhi [NH_N * E_N * 64], g_qlo [NH_N * E_N * 64];
__device__ uint32_t g_khi [NH_N * E_N * 64], g_klo [NH_N * E_N * 64];
__device__ uint32_t g_vthi[NH_N * HD_N * 2048], g_vtlo[NH_N * HD_N * 2048];

// ================= helpers =================
__device__ __forceinline__ uint32_t smem_u32(const void* p) {
    uint32_t a;
    asm("{ .reg .u64 t; cvta.to.shared.u64 t, %1; cvt.u32.u64 %0, t; }"
        : "=r"(a) : "l"(p));
    return a;
}

__device__ __forceinline__ void pack2(float x, float y, uint32_t& hi, uint32_t& lo) {
    __nv_bfloat162 h = __floats2bfloat162_rn(x, y);
    float hx = __bfloat162float(__low2bfloat16(h));
    float hy = __bfloat162float(__high2bfloat16(h));
    __nv_bfloat162 l = __floats2bfloat162_rn(x - hx, y - hy);
    hi = *reinterpret_cast<uint32_t*>(&h);
    lo = *reinterpret_cast<uint32_t*>(&l);
}

__device__ __forceinline__ void mma_bf16(float* d, const uint32_t* a, const uint32_t* b) {
    asm volatile(
        "mma.sync.aligned.m16n8k16.row.col.f32.bf16.bf16.f32 "
        "{%0,%1,%2,%3}, {%4,%5,%6,%7}, {%8,%9}, {%0,%1,%2,%3};"
        : "+f"(d[0]), "+f"(d[1]), "+f"(d[2]), "+f"(d[3])
        : "r"(a[0]), "r"(a[1]), "r"(a[2]), "r"(a[3]),
          "r"(b[0]), "r"(b[1]));
}

__device__ __forceinline__ void ldm_x4(uint32_t* r, uint32_t addr) {
    asm volatile("ldmatrix.sync.aligned.m8n8.x4.shared.b16 {%0,%1,%2,%3}, [%4];"
        : "=r"(r[0]), "=r"(r[1]), "=r"(r[2]), "=r"(r[3]) : "r"(addr));
}
__device__ __forceinline__ void ldm_x2(uint32_t* r, uint32_t addr) {
    asm volatile("ldmatrix.sync.aligned.m8n8.x2.shared.b16 {%0,%1}, [%2];"
        : "=r"(r[0]), "=r"(r[1]) : "r"(addr));
}

__device__ __forceinline__ void cpasync16(uint32_t saddr, const void* g) {
    asm volatile("cp.async.cg.shared.global [%0], [%1], 16;" :: "r"(saddr), "l"(g));
}
#define CP_COMMIT() asm volatile("cp.async.commit_group;" ::: "memory")
#define CP_WAIT1()  asm volatile("cp.async.wait_group 1;" ::: "memory")
#define CP_WAIT0()  asm volatile("cp.async.wait_group 0;" ::: "memory")

// ================= pre-packed bf16x3 GEMM, cp.async double-buffered =====
// C[M,N] = A[M,K] @ B[N,K]^T + bias. A/B given as packed hi/lo planes.
// CTA 128x128, 8 warps 2x4, warp 64x32. K chunk 32 (16 words).
#define WSTR 20
#define CH_WORDS (128 * WSTR)                 // 2560 words/plane/buffer
#define GEMM_SMEM_BYTES (2 * 4 * CH_WORDS * 4)  // 81920

// EPI: 0 = fp32, 1 = fp32+relu, 2 = packed planes + relu
template <int EPI>
__global__ __launch_bounds__(256) void gemm_pk(
    const uint32_t* __restrict__ Ahi, const uint32_t* __restrict__ Alo,
    const uint32_t* __restrict__ Bhi, const uint32_t* __restrict__ Blo,
    const float* __restrict__ bias,
    float* __restrict__ C, uint32_t* __restrict__ Chi, uint32_t* __restrict__ Clo,
    int N, int K)
{
    extern __shared__ uint32_t smw[];
    const uint32_t sb = smem_u32(smw);
    const int tid  = threadIdx.x;
    const int lane = tid & 31;
    const int wid  = tid >> 5;
    const int wm64 = (wid >> 2) << 6;
    const int wn32 = (wid & 3) << 5;
    const int bm = blockIdx.y << 7;
    const int bn = blockIdx.x << 7;
    const int Kw = K >> 1;
    const int NKC = K >> 5;

    float acc[4][4][4];
#pragma unroll
    for (int mt = 0; mt < 4; mt++)
#pragma unroll
        for (int nt = 0; nt < 4; nt++)
#pragma unroll
            for (int c = 0; c < 4; c++) acc[mt][nt][c] = 0.f;

    // stage chunk kc into buffer buf
    auto stage = [&](int kc, int buf) {
        const uint32_t base = (uint32_t)buf * (4 * CH_WORDS);
        const int kcw = kc << 4;
#pragma unroll
        for (int j = 0; j < 2; j++) {
            int idx = tid + (j << 8);            // 0..511
            int r = idx >> 2, w4 = (idx & 3) << 2;
            uint32_t so = base + (uint32_t)(r * WSTR + w4);
            size_t ga = (size_t)(bm + r) * Kw + kcw + w4;
            size_t gb = (size_t)(bn + r) * Kw + kcw + w4;
            cpasync16(sb + (so << 2),                     Ahi + ga);
            cpasync16(sb + ((so + CH_WORDS) << 2),        Alo + ga);
            cpasync16(sb + ((so + 2 * CH_WORDS) << 2),    Bhi + gb);
            cpasync16(sb + ((so + 3 * CH_WORDS) << 2),    Blo + gb);
        }
    };

    stage(0, 0);
    CP_COMMIT();

    for (int kc = 0; kc < NKC; kc++) {
        if (kc + 1 < NKC) {
            stage(kc + 1, (kc + 1) & 1);
            CP_COMMIT();
            CP_WAIT1();
        } else {
            CP_WAIT0();
        }
        __syncthreads();

        const uint32_t bb = (uint32_t)(kc & 1) * (4 * CH_WORDS);
#pragma unroll
        for (int ks = 0; ks < 2; ks++) {
            const int kw = ks << 3;
            uint32_t ahi[4][4], alo[4][4];
#pragma unroll
            for (int mt = 0; mt < 4; mt++) {
                uint32_t wo = bb + (uint32_t)((wm64 + (mt << 4) + (lane & 15)) * WSTR
                                              + kw + ((lane >> 4) << 2));
                ldm_x4(ahi[mt], sb + (wo << 2));
                ldm_x4(alo[mt], sb + ((wo + CH_WORDS) << 2));
            }
            uint32_t bhi[4][2], blo[4][2];
#pragma unroll
            for (int nt = 0; nt < 4; nt++) {
                uint32_t wo = bb + (uint32_t)((wn32 + (nt << 3) + (lane & 7)) * WSTR
                                              + kw + (((lane >> 3) & 1) << 2));
                ldm_x2(bhi[nt], sb + ((wo + 2 * CH_WORDS) << 2));
                ldm_x2(blo[nt], sb + ((wo + 3 * CH_WORDS) << 2));
            }
#pragma unroll
            for (int mt = 0; mt < 4; mt++)
#pragma unroll
                for (int nt = 0; nt < 4; nt++)
                    mma_bf16(acc[mt][nt], ahi[mt], bhi[nt]);
#pragma unroll
            for (int mt = 0; mt < 4; mt++)
#pragma unroll
                for (int nt = 0; nt < 4; nt++)
                    mma_bf16(acc[mt][nt], ahi[mt], blo[nt]);
#pragma unroll
            for (int mt = 0; mt < 4; mt++)
#pragma unroll
                for (int nt = 0; nt < 4; nt++)
                    mma_bf16(acc[mt][nt], alo[mt], bhi[nt]);
        }
        __syncthreads();
    }

    // ---- epilogue ----
#pragma unroll
    for (int mt = 0; mt < 4; mt++) {
        int row0 = bm + wm64 + (mt << 4) + (lane >> 2);
#pragma unroll
        for (int nt = 0; nt < 4; nt++) {
            int col0 = bn + wn32 + (nt << 3) + ((lane & 3) << 1);
            float b0 = bias[col0], b1 = bias[col0 + 1];
            float v00 = acc[mt][nt][0] + b0, v01 = acc[mt][nt][1] + b1;
            float v10 = acc[mt][nt][2] + b0, v11 = acc[mt][nt][3] + b1;
            if (EPI >= 1) {
                v00 = fmaxf(v00, 0.f); v01 = fmaxf(v01, 0.f);
                v10 = fmaxf(v10, 0.f); v11 = fmaxf(v11, 0.f);
            }
            if (EPI == 2) {
                int Nw = N >> 1;
                uint32_t h, l;
                pack2(v00, v01, h, l);
                Chi[(size_t)row0 * Nw + (col0 >> 1)] = h;
                Clo[(size_t)row0 * Nw + (col0 >> 1)] = l;
                pack2(v10, v11, h, l);
                Chi[(size_t)(row0 + 8) * Nw + (col0 >> 1)] = h;
                Clo[(size_t)(row0 + 8) * Nw + (col0 >> 1)] = l;
            } else {
                *(float2*)(C + (size_t)row0 * N + col0) = make_float2(v00, v01);
                *(float2*)(C + (size_t)(row0 + 8) * N + col0) = make_float2(v10, v11);
            }
        }
    }
}

// ---------------- zero ----------------
__global__ void zero_kernel(float* __restrict__ p, int n) {
    int i = blockIdx.x * blockDim.x + threadIdx.x;
    if (i < n) p[i] = 0.f;
}

// ---------------- generic pair-split ----------------
__global__ __launch_bounds__(256) void split_pairs_kernel(
    const float* __restrict__ src, uint32_t* __restrict__ hi,
    uint32_t* __restrict__ lo, int npairs)
{
    int i = blockIdx.x * 256 + threadIdx.x;
    if (i >= npairs) return;
    float2 v = *(const float2*)(src + (size_t)i * 2);
    uint32_t h, l;
    pack2(v.x, v.y, h, l);
    hi[i] = h; lo[i] = l;
}

// ---------------- combined weight split ----------------
__global__ __launch_bounds__(256) void split_weights_kernel(
    const float* __restrict__ w0, const float* __restrict__ w1,
    const float* __restrict__ w2, const float* __restrict__ w3,
    const float* __restrict__ w4, const float* __restrict__ w5,
    const float* __restrict__ w6)
{
    int i = blockIdx.x * 256 + threadIdx.x;
    if (i >= WTOTAL) return;
    const int offs[8] = {WOFF_MSG, WOFF_IH, WOFF_HH, WOFF_INP,
                         WOFF_OUTP, WOFF_LIN, WOFF_F1, WTOTAL};
    const float* srcs[7] = {w0, w1, w2, w3, w4, w5, w6};
    int s = 0;
#pragma unroll
    for (int k = 1; k < 7; k++) if (i >= offs[k]) s = k;
    int li = i - offs[s];
    float2 v = *(const float2*)(srcs[s] + (size_t)li * 2);
    uint32_t h, l;
    pack2(v.x, v.y, h, l);
    g_whi[i] = h; g_wlo[i] = l;
}

// ---------------- edge-index dtype detection ----------------
__global__ void detect_idx_kernel(const int* __restrict__ ei32) {
    if (threadIdx.x == 0 && blockIdx.x == 0) {
        int allzero = 1;
#pragma unroll
        for (int i = 1; i < 16; i += 2)
            if (ei32[i] != 0) allzero = 0;
        g_idx64_flag = allzero;
    }
}

// ---------------- scatter-add ----------------
__global__ void scatter_add_kernel(const void* __restrict__ ei) {
    int e = blockIdx.x;
    int dst;
    if (g_idx64_flag)
        dst = (int)((const long long*)ei)[E_N + e];
    else
        dst = ((const int*)ei)[E_N + e];
    if ((unsigned)dst >= (unsigned)E_N) return;
    const float* src = g_msg + (size_t)e * H_N;
    float* d = g_agg + (size_t)dst * H_N;
    for (int i = threadIdx.x; i < H_N; i += blockDim.x)
        atomicAdd(&d[i], src[i]);
}

// ---------------- GRU elementwise (+ h planes) ----------------
__global__ __launch_bounds__(256) void gru_kernel(const float* __restrict__ x) {
    int idx = blockIdx.x * 256 + threadIdx.x;   // < E_N * 256
    if (idx >= E_N * 256) return;
    int e = idx >> 8, i = (idx & 255) << 1;
    const float* gi = g_gi + (size_t)e * H3_N;
    const float* gh = g_gh + (size_t)e * H3_N;
    float h2[2];
#pragma unroll
    for (int u = 0; u < 2; u++) {
        int c = i + u;
        float r = 1.f / (1.f + __expf(-(gi[c] + gh[c])));
        float z = 1.f / (1.f + __expf(-(gi[H_N + c] + gh[H_N + c])));
        float n = tanhf(gi[2 * H_N + c] + r * gh[2 * H_N + c]);
        h2[u] = (1.f - z) * n + z * x[(size_t)e * H_N + c];
        g_h[(size_t)e * H_N + c] = h2[u];
    }
    uint32_t h, l;
    pack2(h2[0], h2[1], h, l);
    g_hhi[idx] = h; g_hlo[idx] = l;
}

// ---------------- split Q/K per-head (from fp32 qkv) ----------------
__global__ __launch_bounds__(256) void split_qk_kernel() {
    int idx = blockIdx.x * 256 + threadIdx.x;   // < E_N * 256
    if (idx >= E_N * 256) return;
    int e = idx >> 8, p = idx & 255;
    int head = p >> 6, dp = p & 63;
    const float scale = 0.08838834764831845f;
    size_t src = (size_t)e * H3_N + head * HD_N + (dp << 1);
    uint32_t h, l;
    pack2(g_qkv[src] * scale, g_qkv[src + 1] * scale, h, l);
    size_t dst = ((size_t)head * E_N + e) * 64 + dp;
    g_qhi[dst] = h; g_qlo[dst] = l;
    pack2(g_qkv[src + H_N], g_qkv[src + H_N + 1], h, l);
    g_khi[dst] = h; g_klo[dst] = l;
}

// ---------------- split V transposed ----------------
__global__ __launch_bounds__(256) void split_vt_kernel() {
    int idx = blockIdx.x * 256 + threadIdx.x;   // < 2048 * H_N
    if (idx >= 2048 * H_N) return;
    int ep = idx >> 9, c = idx & 511;
    int head = c >> 7, d = c & 127;
    float v0 = g_qkv[(size_t)(2 * ep) * H3_N + 2 * H_N + c];
    float v1 = g_qkv[(size_t)(2 * ep + 1) * H3_N + 2 * H_N + c];
    uint32_t h, l;
    pack2(v0, v1, h, l);
    size_t dst = ((size_t)head * HD_N + d) * 2048 + ep;
    g_vthi[dst] = h; g_vtlo[dst] = l;
}

// ---------------- flash-attention, bf16x3 mma ----------------
#define AQ_STR 68
#define AK_STR 68
#define AV_STR 20
#define AS_STR 36
#define AT_QHI 0
#define AT_QLO (AT_QHI + 128 * AQ_STR)
#define AT_KHI (AT_QLO + 128 * AQ_STR)
#define AT_KLO (AT_KHI + 32 * AK_STR)
#define AT_VHI (AT_KLO + 32 * AK_STR)
#define AT_VLO (AT_VHI + 128 * AV_STR)
#define AT_SS  (AT_VLO + 128 * AV_STR)
#define AT_MS  (AT_SS + 128 * AS_STR)
#define AT_LS  (AT_MS + 128)
#define AT_AS  (AT_LS + 128)
#define AT_TOTAL (AT_AS + 128)
#define ATTN_SMEM_BYTES (AT_TOTAL * 4)

__global__ __launch_bounds__(256) void attn_bf16_kernel() {
    extern __shared__ uint32_t smw[];
    const uint32_t sb = smem_u32(smw);
    float* SS  = (float*)(smw + AT_SS);
    float* m_s = (float*)(smw + AT_MS);
    float* l_s = (float*)(smw + AT_LS);
    float* a_s = (float*)(smw + AT_AS);

    const int t = threadIdx.x;
    const int lane = t & 31;
    const int w = t >> 5;
    const int gid = lane >> 2;
    const int qid = lane & 3;
    const int r0 = (w << 4) + gid;
    const int q0 = blockIdx.x << 7;
    const int head = blockIdx.y;

    {
        size_t qb = ((size_t)head * E_N + q0) * 64;
        for (int i = t; i < 2048; i += 256) {
            int r = i >> 4, w4 = (i & 15) << 2;
            *(uint4*)(smw + AT_QHI + r * AQ_STR + w4) = *(const uint4*)&g_qhi[qb + r * 64 + w4];
            *(uint4*)(smw + AT_QLO + r * AQ_STR + w4) = *(const uint4*)&g_qlo[qb + r * 64 + w4];
        }
    }
    if (t < 128) { m_s[t] = -1e30f; l_s[t] = 0.f; }

    float o[16][4];
#pragma unroll
    for (int nf = 0; nf < 16; nf++)
#pragma unroll
        for (int c = 0; c < 4; c++) o[nf][c] = 0.f;

    __syncthreads();

    for (int j0 = 0; j0 < E_N; j0 += 32) {
        {
            size_t kb = ((size_t)head * E_N + j0) * 64;
            for (int i = t; i < 512; i += 256) {
                int r = i >> 4, w4 = (i & 15) << 2;
                *(uint4*)(smw + AT_KHI + r * AK_STR + w4) = *(const uint4*)&g_khi[kb + r * 64 + w4];
                *(uint4*)(smw + AT_KLO + r * AK_STR + w4) = *(const uint4*)&g_klo[kb + r * 64 + w4];
            }
            size_t vb = (size_t)head * HD_N * 2048 + (j0 >> 1);
            for (int i = t; i < 512; i += 256) {
                int r = i >> 2, w4 = (i & 3) << 2;
                *(uint4*)(smw + AT_VHI + r * AV_STR + w4) =
                    *(const uint4*)&g_vthi[vb + (size_t)r * 2048 + w4];
                *(uint4*)(smw + AT_VLO + r * AV_STR + w4) =
                    *(const uint4*)&g_vtlo[vb + (size_t)r * 2048 + w4];
            }
        }
        __syncthreads();

        float sacc[4][4];
#pragma unroll
        for (int nf = 0; nf < 4; nf++)
#pragma unroll
            for (int c = 0; c < 4; c++) sacc[nf][c] = 0.f;

#pragma unroll
        for (int ks = 0; ks < 8; ks++) {
            const int kw = ks << 3;
            uint32_t ahi[4], alo[4];
            uint32_t ao = (uint32_t)(((AT_QHI + ((w << 4) + (lane & 15)) * AQ_STR
                                       + kw + ((lane >> 4) << 2))) << 2);
            ldm_x4(ahi, sb + ao);
            ldm_x4(alo, sb + ao + (uint32_t)((AT_QLO - AT_QHI) << 2));
#pragma unroll
            for (int nf = 0; nf < 4; nf++) {
                uint32_t bo = (uint32_t)(((AT_KHI + ((nf << 3) + (lane & 7)) * AK_STR
                                           + kw + (((lane >> 3) & 1) << 2))) << 2);
                uint32_t bh[2], bl[2];
                ldm_x2(bh, sb + bo);
                ldm_x2(bl, sb + bo + (uint32_t)((AT_KLO - AT_KHI) << 2));
                mma_bf16(sacc[nf], ahi, bh);
                mma_bf16(sacc[nf], ahi, bl);
                mma_bf16(sacc[nf], alo, bh);
            }
        }
#pragma unroll
        for (int nf = 0; nf < 4; nf++) {
            int cb = (nf << 3) + (qid << 1);
            SS[r0 * AS_STR + cb]           = sacc[nf][0];
            SS[r0 * AS_STR + cb + 1]       = sacc[nf][1];
            SS[(r0 + 8) * AS_STR + cb]     = sacc[nf][2];
            SS[(r0 + 8) * AS_STR + cb + 1] = sacc[nf][3];
        }
        __syncthreads();

        {
            int r = t >> 1, cb = (t & 1) << 4;
            float* srow = &SS[r * AS_STR + cb];
            float mloc = -1e30f;
#pragma unroll
            for (int i = 0; i < 16; i++) mloc = fmaxf(mloc, srow[i]);
            mloc = fmaxf(mloc, __shfl_xor_sync(0xffffffffu, mloc, 1));
            float mold = m_s[r];
            float mnew = fmaxf(mold, mloc);
            float ssum = 0.f;
#pragma unroll
            for (int i = 0; i < 16; i++) {
                float p = __expf(srow[i] - mnew);
                srow[i] = p;
                ssum += p;
            }
            ssum += __shfl_xor_sync(0xffffffffu, ssum, 1);
            if (!(t & 1)) {
                float alpha = __expf(mold - mnew);
                m_s[r] = mnew;
                a_s[r] = alpha;
                l_s[r] = l_s[r] * alpha + ssum;
            }
        }
        __syncthreads();

        {
            float al0 = a_s[r0], al1 = a_s[r0 + 8];
#pragma unroll
            for (int nf = 0; nf < 16; nf++) {
                o[nf][0] *= al0; o[nf][1] *= al0;
                o[nf][2] *= al1; o[nf][3] *= al1;
            }
        }
#pragma unroll
        for (int ks = 0; ks < 2; ks++) {
            const int k0 = ks << 4;
            float p00 = SS[r0 * AS_STR + k0 + (qid << 1)];
            float p01 = SS[r0 * AS_STR + k0 + (qid << 1) + 1];
            float p10 = SS[(r0 + 8) * AS_STR + k0 + (qid << 1)];
            float p11 = SS[(r0 + 8) * AS_STR + k0 + (qid << 1) + 1];
            float p20 = SS[r0 * AS_STR + k0 + 8 + (qid << 1)];
            float p21 = SS[r0 * AS_STR + k0 + 8 + (qid << 1) + 1];
            float p30 = SS[(r0 + 8) * AS_STR + k0 + 8 + (qid << 1)];
            float p31 = SS[(r0 + 8) * AS_STR + k0 + 8 + (qid << 1) + 1];
            uint32_t phi[4], plo[4];
            pack2(p00, p01, phi[0], plo[0]);
            pack2(p10, p11, phi[1], plo[1]);
            pack2(p20, p21, phi[2], plo[2]);
            pack2(p30, p31, phi[3], plo[3]);
#pragma unroll
            for (int nf = 0; nf < 16; nf++) {
                uint32_t bo = (uint32_t)(((AT_VHI + ((nf << 3) + (lane & 7)) * AV_STR
                                           + (ks << 3) + (((lane >> 3) & 1) << 2))) << 2);
                uint32_t bh[2], bl[2];
                ldm_x2(bh, sb + bo);
                ldm_x2(bl, sb + bo + (uint32_t)((AT_VLO - AT_VHI) << 2));
                mma_bf16(o[nf], phi, bh);
                mma_bf16(o[nf], phi, bl);
                mma_bf16(o[nf], plo, bh);
            }
        }
        __syncthreads();
    }

    // ---- epilogue: write packed attn planes directly ----
    {
        float inv0 = 1.f / l_s[r0];
        float inv1 = 1.f / l_s[r0 + 8];
#pragma unroll
        for (int nf = 0; nf < 16; nf++) {
            int cw = head * 64 + (nf << 2) + qid;
            uint32_t h, l;
            pack2(o[nf][0] * inv0, o[nf][1] * inv0, h, l);
            g_attnhi[(size_t)(q0 + r0) * 256 + cw] = h;
            g_attnlo[(size_t)(q0 + r0) * 256 + cw] = l;
            pack2(o[nf][2] * inv1, o[nf][3] * inv1, h, l);
            g_attnhi[(size_t)(q0 + r0 + 8) * 256 + cw] = h;
            g_attnlo[(size_t)(q0 + r0 + 8) * 256 + cw] = l;
        }
    }
}

// ---------------- residual + LayerNorm (writes yn planes) ----------------
__global__ __launch_bounds__(256) void ln_kernel(const float* __restrict__ ln_g,
                                                 const float* __restrict__ ln_b) {
    __shared__ float reda[8], redb[8];
    int e = blockIdx.x;
    int t = threadIdx.x;
    const float* yp = g_yprj + (size_t)e * H_N;
    const float* hp = g_h + (size_t)e * H_N;
    int i0 = t << 1, i1 = i0 + 1;
    float v0 = yp[i0] + hp[i0];
    float v1 = yp[i1] + hp[i1];
    float s = v0 + v1, s2 = v0 * v0 + v1 * v1;
#pragma unroll
    for (int o = 16; o > 0; o >>= 1) {
        s  += __shfl_down_sync(0xffffffffu, s, o);
        s2 += __shfl_down_sync(0xffffffffu, s2, o);
    }
    int w = t >> 5;
    if ((t & 31) == 0) { reda[w] = s; redb[w] = s2; }
    __syncthreads();
    if (t < 8) {
        s = reda[t]; s2 = redb[t];
#pragma unroll
        for (int o = 4; o > 0; o >>= 1) {
            s  += __shfl_down_sync(0xffu, s, o);
            s2 += __shfl_down_sync(0xffu, s2, o);
        }
        if (t == 0) { reda[0] = s; redb[0] = s2; }
    }
    __syncthreads();
    float mu = reda[0] * (1.f / H_N);
    float var = redb[0] * (1.f / H_N) - mu * mu;
    float rstd = rsqrtf(var + 1e-5f);
    float y0 = (v0 - mu) * rstd * ln_g[i0] + ln_b[i0];
    float y1 = (v1 - mu) * rstd * ln_g[i1] + ln_b[i1];
    uint32_t h, l;
    pack2(y0, y1, h, l);
    g_ynhi[(size_t)e * 256 + t] = h;
    g_ynlo[(size_t)e * 256 + t] = l;
}

// ---------------- final dot ----------------
__global__ __launch_bounds__(256) void final_kernel(const float* __restrict__ W2,
                                                    const float* __restrict__ b2,
                                                    float* __restrict__ out) {
    __shared__ float red[8];
    int e = blockIdx.x;
    const float* fp = g_f + (size_t)e * FFN_N;
    float s = 0.f;
    for (int i = threadIdx.x; i < FFN_N; i += 256) s += fp[i] * W2[i];
#pragma unroll
    for (int o = 16; o > 0; o >>= 1) s += __shfl_down_sync(0xffffffffu, s, o);
    int w = threadIdx.x >> 5;
    if ((threadIdx.x & 31) == 0) red[w] = s;
    __syncthreads();
    if (threadIdx.x < 8) {
        s = red[threadIdx.x];
#pragma unroll
        for (int o = 4; o > 0; o >>= 1) s += __shfl_down_sync(0xffu, s, o);
        if (threadIdx.x == 0) out[e] = s + b2[0];
    }
}

// ---------------- launcher ----------------
extern "C" void kernel_launch(void* const* d_in, const int* in_sizes, int n_in,
                              void* d_out, int out_size) {
    const float* x       = (const float*)d_in[0];
    const void*  ei      = d_in[1];
    const float* W_msg   = (const float*)d_in[2];
    const float* b_msg   = (const float*)d_in[3];
    const float* W_ih    = (const float*)d_in[4];
    const float* b_ih    = (const float*)d_in[5];
    const float* W_hh    = (const float*)d_in[6];
    const float* b_hh    = (const float*)d_in[7];
    const float* W_inp   = (const float*)d_in[8];
    const float* b_inp   = (const float*)d_in[9];
    const float* W_outp  = (const float*)d_in[10];
    const float* b_outp  = (const float*)d_in[11];
    const float* ln_g    = (const float*)d_in[12];
    const float* ln_b    = (const float*)d_in[13];
    const float* W_lin   = (const float*)d_in[14];
    const float* b_lin   = (const float*)d_in[15];
    const float* W_f1    = (const float*)d_in[16];
    const float* b_f1    = (const float*)d_in[17];
    const float* W_f2    = (const float*)d_in[18];
    const float* b_f2    = (const float*)d_in[19];
    float* out = (float*)d_out;

    float *p_msg, *p_agg, *p_gi, *p_gh, *p_qkv, *p_yprj, *p_f;
    cudaGetSymbolAddress((void**)&p_msg,  g_msg);
    cudaGetSymbolAddress((void**)&p_agg,  g_agg);
    cudaGetSymbolAddress((void**)&p_gi,   g_gi);
    cudaGetSymbolAddress((void**)&p_gh,   g_gh);
    cudaGetSymbolAddress((void**)&p_qkv,  g_qkv);
    cudaGetSymbolAddress((void**)&p_yprj, g_yprj);
    cudaGetSymbolAddress((void**)&p_f,    g_f);
    uint32_t *p_xhi, *p_xlo, *p_agghi, *p_agglo, *p_hhi, *p_hlo;
    uint32_t *p_attnhi, *p_attnlo, *p_ynhi, *p_ynlo, *p_gacthi, *p_gactlo;
    uint32_t *p_whi, *p_wlo;
    cudaGetSymbolAddress((void**)&p_xhi,    g_xhi);
    cudaGetSymbolAddress((void**)&p_xlo,    g_xlo);
    cudaGetSymbolAddress((void**)&p_agghi,  g_agghi);
    cudaGetSymbolAddress((void**)&p_agglo,  g_agglo);
    cudaGetSymbolAddress((void**)&p_hhi,    g_hhi);
    cudaGetSymbolAddress((void**)&p_hlo,    g_hlo);
    cudaGetSymbolAddress((void**)&p_attnhi, g_attnhi);
    cudaGetSymbolAddress((void**)&p_attnlo, g_attnlo);
    cudaGetSymbolAddress((void**)&p_ynhi,   g_ynhi);
    cudaGetSymbolAddress((void**)&p_ynlo,   g_ynlo);
    cudaGetSymbolAddress((void**)&p_gacthi, g_gacthi);
    cudaGetSymbolAddress((void**)&p_gactlo, g_gactlo);
    cudaGetSymbolAddress((void**)&p_whi,    g_whi);
    cudaGetSymbolAddress((void**)&p_wlo,    g_wlo);

    cudaFuncSetAttribute(gemm_pk<0>, cudaFuncAttributeMaxDynamicSharedMemorySize, GEMM_SMEM_BYTES);
    cudaFuncSetAttribute(gemm_pk<1>, cudaFuncAttributeMaxDynamicSharedMemorySize, GEMM_SMEM_BYTES);
    cudaFuncSetAttribute(gemm_pk<2>, cudaFuncAttributeMaxDynamicSharedMemorySize, GEMM_SMEM_BYTES);
    cudaFuncSetAttribute(attn_bf16_kernel, cudaFuncAttributeMaxDynamicSharedMemorySize, ATTN_SMEM_BYTES);

    // 0) detect edge_index dtype; splits of inputs
    detect_idx_kernel<<<1, 32>>>((const int*)ei);
    zero_kernel<<<(E_N * H_N + 255) / 256, 256>>>(p_agg, E_N * H_N);
    split_pairs_kernel<<<(E_N * 256) / 256, 256>>>(x, p_xhi, p_xlo, E_N * 256);
    split_weights_kernel<<<(WTOTAL + 255) / 256, 256>>>(W_msg, W_ih, W_hh, W_inp, W_outp, W_lin, W_f1);
    // 2) msg = relu(x @ W_msg^T + b)
    gemm_pk<1><<<dim3(H_N / 128, 32), 256, GEMM_SMEM_BYTES>>>(
        p_xhi, p_xlo, p_whi + WOFF_MSG, p_wlo + WOFF_MSG, b_msg, p_msg, nullptr, nullptr, H_N, H_N);
    // 3) scatter-add, then split agg
    scatter_add_kernel<<<E_N, 128>>>(ei);
    split_pairs_kernel<<<(E_N * 256) / 256, 256>>>(p_agg, p_agghi, p_agglo, E_N * 256);
    // 4) gi, gh
    gemm_pk<0><<<dim3(H3_N / 128, 32), 256, GEMM_SMEM_BYTES>>>(
        p_agghi, p_agglo, p_whi + WOFF_IH, p_wlo + WOFF_IH, b_ih, p_gi, nullptr, nullptr, H3_N, H_N);
    gemm_pk<0><<<dim3(H3_N / 128, 32), 256, GEMM_SMEM_BYTES>>>(
        p_xhi, p_xlo, p_whi + WOFF_HH, p_wlo + WOFF_HH, b_hh, p_gh, nullptr, nullptr, H3_N, H_N);
    // 5) GRU (writes h fp32 + planes)
    gru_kernel<<<(E_N * 256) / 256, 256>>>(x);
    // 6) qkv
    gemm_pk<0><<<dim3(H3_N / 128, 32), 256, GEMM_SMEM_BYTES>>>(
        p_hhi, p_hlo, p_whi + WOFF_INP, p_wlo + WOFF_INP, b_inp, p_qkv, nullptr, nullptr, H3_N, H_N);
    // 7) splits + attention (attention writes attn planes)
    split_qk_kernel<<<(E_N * 256) / 256, 256>>>();
    split_vt_kernel<<<(2048 * H_N) / 256, 256>>>();
    attn_bf16_kernel<<<dim3(E_N / 128, NH_N), 256, ATTN_SMEM_BYTES>>>();
    // 8) out-proj
    gemm_pk<0><<<dim3(H_N / 128, 32), 256, GEMM_SMEM_BYTES>>>(
        p_attnhi, p_attnlo, p_whi + WOFF_OUTP, p_wlo + WOFF_OUTP, b_outp, p_yprj, nullptr, nullptr, H_N, H_N);
    // 9) residual + LN (writes yn planes)
    ln_kernel<<<E_N, 256>>>(ln_g, ln_b);
    // 10) g = relu(yn @ W_lin^T + b) -> packed gact planes
    gemm_pk<2><<<dim3(H_N / 128, 32), 256, GEMM_SMEM_BYTES>>>(
        p_ynhi, p_ynlo, p_whi + WOFF_LIN, p_wlo + WOFF_LIN, b_lin, nullptr, p_gacthi, p_gactlo, H_N, H_N);
    // 11) f = relu(g @ W_f1^T + b_f1) fp32
    gemm_pk<1><<<dim3(FFN_N / 128, 32), 256, GEMM_SMEM_BYTES>>>(
        p_gacthi, p_gactlo, p_whi + WOFF_F1, p_wlo + WOFF_F1, b_f1, p_f, nullptr, nullptr, FFN_N, H_N);
    // 12) out
    final_kernel<<<E_N, 256>>>(W_f2, b_f2, out);
}

// round 8
// speedup vs baseline: 1.0547x; 1.0547x over previous
#include <cuda_runtime.h>
#include <cuda_bf16.h>
#include <math.h>
#include <stdint.h>

#define E_N   4096
#define H_N   512
#define NH_N  4
#define HD_N  128
#define FFN_N 1024
#define H3_N  1536

// ---------------- fp32 scratch ----------------
__device__ float g_msg [E_N * H_N];
__device__ float g_agg [E_N * H_N];
__device__ float g_gi  [E_N * H3_N];
__device__ float g_gh  [E_N * H3_N];
__device__ float g_h   [E_N * H_N];
__device__ float g_qkv [E_N * H3_N];
__device__ float g_yprj[E_N * H_N];
__device__ float g_f   [E_N * FFN_N];
__device__ int   g_idx64_flag;

// ---------------- packed bf16x2 hi/lo planes ----------------
__device__ uint32_t g_xhi   [E_N * 256], g_xlo   [E_N * 256];
__device__ uint32_t g_agghi [E_N * 256], g_agglo [E_N * 256];
__device__ uint32_t g_hhi   [E_N * 256], g_hlo   [E_N * 256];
__device__ uint32_t g_attnhi[E_N * 256], g_attnlo[E_N * 256];
__device__ uint32_t g_ynhi  [E_N * 256], g_ynlo  [E_N * 256];
__device__ uint32_t g_gacthi[E_N * 256], g_gactlo[E_N * 256];
// weights combined (word offsets / 1 word = 1 bf16x2 pair)
#define WOFF_MSG  0
#define WOFF_IH   131072
#define WOFF_HH   524288
#define WOFF_INP  917504
#define WOFF_OUTP 1310720
#define WOFF_LIN  1441792
#define WOFF_F1   1572864
#define WTOTAL    1835008
__device__ uint32_t g_whi[WTOTAL], g_wlo[WTOTAL];
// attention planes
__device__ uint32_t g_qhi [NH_N * E_N * 64], g_qlo [NH_N * E_N * 64];
__device__ uint32_t g_khi [NH_N * E_N * 64], g_klo [NH_N * E_N * 64];
__device__ uint32_t g_vthi[NH_N * HD_N * 2048], g_vtlo[NH_N * HD_N * 2048];

// ================= helpers =================
__device__ __forceinline__ uint32_t smem_u32(const void* p) {
    uint32_t a;
    asm("{ .reg .u64 t; cvta.to.shared.u64 t, %1; cvt.u32.u64 %0, t; }"
        : "=r"(a) : "l"(p));
    return a;
}

__device__ __forceinline__ void pack2(float x, float y, uint32_t& hi, uint32_t& lo) {
    __nv_bfloat162 h = __floats2bfloat162_rn(x, y);
    float hx = __bfloat162float(__low2bfloat16(h));
    float hy = __bfloat162float(__high2bfloat16(h));
    __nv_bfloat162 l = __floats2bfloat162_rn(x - hx, y - hy);
    hi = *reinterpret_cast<uint32_t*>(&h);
    lo = *reinterpret_cast<uint32_t*>(&l);
}

__device__ __forceinline__ void mma_bf16(float* d, const uint32_t* a, const uint32_t* b) {
    asm volatile(
        "mma.sync.aligned.m16n8k16.row.col.f32.bf16.bf16.f32 "
        "{%0,%1,%2,%3}, {%4,%5,%6,%7}, {%8,%9}, {%0,%1,%2,%3};"
        : "+f"(d[0]), "+f"(d[1]), "+f"(d[2]), "+f"(d[3])
        : "r"(a[0]), "r"(a[1]), "r"(a[2]), "r"(a[3]),
          "r"(b[0]), "r"(b[1]));
}

__device__ __forceinline__ void ldm_x4(uint32_t* r, uint32_t addr) {
    asm volatile("ldmatrix.sync.aligned.m8n8.x4.shared.b16 {%0,%1,%2,%3}, [%4];"
        : "=r"(r[0]), "=r"(r[1]), "=r"(r[2]), "=r"(r[3]) : "r"(addr));
}
__device__ __forceinline__ void ldm_x2(uint32_t* r, uint32_t addr) {
    asm volatile("ldmatrix.sync.aligned.m8n8.x2.shared.b16 {%0,%1}, [%2];"
        : "=r"(r[0]), "=r"(r[1]) : "r"(addr));
}

__device__ __forceinline__ void cpasync16(uint32_t saddr, const void* g) {
    asm volatile("cp.async.cg.shared.global [%0], [%1], 16;" :: "r"(saddr), "l"(g));
}
#define CP_COMMIT() asm volatile("cp.async.commit_group;" ::: "memory")
#define CP_WAIT0()  asm volatile("cp.async.wait_group 0;" ::: "memory")

// ================= bf16x3 GEMM, cp.async double-buffered, 1 sync/chunk ==
#define WSTR 20
#define CH_WORDS (128 * WSTR)
#define GEMM_SMEM_BYTES (2 * 4 * CH_WORDS * 4)  // 81920

// EPI: 0 = fp32, 1 = fp32+relu, 2 = packed planes + relu
template <int EPI>
__global__ __launch_bounds__(256) void gemm_pk(
    const uint32_t* __restrict__ Ahi, const uint32_t* __restrict__ Alo,
    const uint32_t* __restrict__ Bhi, const uint32_t* __restrict__ Blo,
    const float* __restrict__ bias,
    float* __restrict__ C, uint32_t* __restrict__ Chi, uint32_t* __restrict__ Clo,
    int N, int K)
{
    extern __shared__ uint32_t smw[];
    const uint32_t sb = smem_u32(smw);
    const int tid  = threadIdx.x;
    const int lane = tid & 31;
    const int wid  = tid >> 5;
    const int wm64 = (wid >> 2) << 6;
    const int wn32 = (wid & 3) << 5;
    const int bm = blockIdx.y << 7;
    const int bn = blockIdx.x << 7;
    const int Kw = K >> 1;
    const int NKC = K >> 5;

    float acc[4][4][4];
#pragma unroll
    for (int mt = 0; mt < 4; mt++)
#pragma unroll
        for (int nt = 0; nt < 4; nt++)
#pragma unroll
            for (int c = 0; c < 4; c++) acc[mt][nt][c] = 0.f;

    auto stage = [&](int kc, int buf) {
        const uint32_t base = (uint32_t)buf * (4 * CH_WORDS);
        const int kcw = kc << 4;
#pragma unroll
        for (int j = 0; j < 2; j++) {
            int idx = tid + (j << 8);
            int r = idx >> 2, w4 = (idx & 3) << 2;
            uint32_t so = base + (uint32_t)(r * WSTR + w4);
            size_t ga = (size_t)(bm + r) * Kw + kcw + w4;
            size_t gb = (size_t)(bn + r) * Kw + kcw + w4;
            cpasync16(sb + (so << 2),                  Ahi + ga);
            cpasync16(sb + ((so + CH_WORDS) << 2),     Alo + ga);
            cpasync16(sb + ((so + 2 * CH_WORDS) << 2), Bhi + gb);
            cpasync16(sb + ((so + 3 * CH_WORDS) << 2), Blo + gb);
        }
    };

    stage(0, 0);
    CP_COMMIT();

    for (int kc = 0; kc < NKC; kc++) {
        CP_WAIT0();
        __syncthreads();   // buf kc published; all warps done reading buf kc^1
        if (kc + 1 < NKC) {
            stage(kc + 1, (kc + 1) & 1);
            CP_COMMIT();
        }
        const uint32_t bb = (uint32_t)(kc & 1) * (4 * CH_WORDS);
#pragma unroll
        for (int ks = 0; ks < 2; ks++) {
            const int kw = ks << 3;
            uint32_t ahi[4][4], alo[4][4];
#pragma unroll
            for (int mt = 0; mt < 4; mt++) {
                uint32_t wo = bb + (uint32_t)((wm64 + (mt << 4) + (lane & 15)) * WSTR
                                              + kw + ((lane >> 4) << 2));
                ldm_x4(ahi[mt], sb + (wo << 2));
                ldm_x4(alo[mt], sb + ((wo + CH_WORDS) << 2));
            }
            uint32_t bhi[4][2], blo[4][2];
#pragma unroll
            for (int nt = 0; nt < 4; nt++) {
                uint32_t wo = bb + (uint32_t)((wn32 + (nt << 3) + (lane & 7)) * WSTR
                                              + kw + (((lane >> 3) & 1) << 2));
                ldm_x2(bhi[nt], sb + ((wo + 2 * CH_WORDS) << 2));
                ldm_x2(blo[nt], sb + ((wo + 3 * CH_WORDS) << 2));
            }
#pragma unroll
            for (int mt = 0; mt < 4; mt++)
#pragma unroll
                for (int nt = 0; nt < 4; nt++)
                    mma_bf16(acc[mt][nt], ahi[mt], bhi[nt]);
#pragma unroll
            for (int mt = 0; mt < 4; mt++)
#pragma unroll
                for (int nt = 0; nt < 4; nt++)
                    mma_bf16(acc[mt][nt], ahi[mt], blo[nt]);
#pragma unroll
            for (int mt = 0; mt < 4; mt++)
#pragma unroll
                for (int nt = 0; nt < 4; nt++)
                    mma_bf16(acc[mt][nt], alo[mt], bhi[nt]);
        }
    }

#pragma unroll
    for (int mt = 0; mt < 4; mt++) {
        int row0 = bm + wm64 + (mt << 4) + (lane >> 2);
#pragma unroll
        for (int nt = 0; nt < 4; nt++) {
            int col0 = bn + wn32 + (nt << 3) + ((lane & 3) << 1);
            float b0 = bias[col0], b1 = bias[col0 + 1];
            float v00 = acc[mt][nt][0] + b0, v01 = acc[mt][nt][1] + b1;
            float v10 = acc[mt][nt][2] + b0, v11 = acc[mt][nt][3] + b1;
            if (EPI >= 1) {
                v00 = fmaxf(v00, 0.f); v01 = fmaxf(v01, 0.f);
                v10 = fmaxf(v10, 0.f); v11 = fmaxf(v11, 0.f);
            }
            if (EPI == 2) {
                int Nw = N >> 1;
                uint32_t h, l;
                pack2(v00, v01, h, l);
                Chi[(size_t)row0 * Nw + (col0 >> 1)] = h;
                Clo[(size_t)row0 * Nw + (col0 >> 1)] = l;
                pack2(v10, v11, h, l);
                Chi[(size_t)(row0 + 8) * Nw + (col0 >> 1)] = h;
                Clo[(size_t)(row0 + 8) * Nw + (col0 >> 1)] = l;
            } else {
                *(float2*)(C + (size_t)row0 * N + col0) = make_float2(v00, v01);
                *(float2*)(C + (size_t)(row0 + 8) * N + col0) = make_float2(v10, v11);
            }
        }
    }
}

// ---------------- zero ----------------
__global__ void zero_kernel(float* __restrict__ p, int n) {
    int i = blockIdx.x * blockDim.x + threadIdx.x;
    if (i < n) p[i] = 0.f;
}

// ---------------- vectorized pair-split: 4 pairs / thread ----------------
__global__ __launch_bounds__(256) void split_pairs_v4(
    const float* __restrict__ src, uint32_t* __restrict__ hi,
    uint32_t* __restrict__ lo, int ngroups)
{
    int i = blockIdx.x * 256 + threadIdx.x;
    if (i >= ngroups) return;
    float4 a = *(const float4*)(src + (size_t)i * 8);
    float4 b = *(const float4*)(src + (size_t)i * 8 + 4);
    uint4 h, l;
    pack2(a.x, a.y, h.x, l.x);
    pack2(a.z, a.w, h.y, l.y);
    pack2(b.x, b.y, h.z, l.z);
    pack2(b.z, b.w, h.w, l.w);
    *(uint4*)(hi + (size_t)i * 4) = h;
    *(uint4*)(lo + (size_t)i * 4) = l;
}

// ---------------- combined weight split (table-driven, uint4) ------------
__global__ __launch_bounds__(256) void split_weights_kernel(
    const float* __restrict__ w0, const float* __restrict__ w1,
    const float* __restrict__ w2, const float* __restrict__ w3,
    const float* __restrict__ w4, const float* __restrict__ w5,
    const float* __restrict__ w6)
{
    int i = blockIdx.x * 256 + threadIdx.x;       // group of 4 pairs
    if (i >= WTOTAL / 4) return;
    // 131072-word units (32768 groups each): unit -> segment
    const unsigned char segtab[14] = {0,1,1,1,2,2,2,3,3,3,4,5,6,6};
    const int segbase[7] = {0, 32768, 131072, 229376, 327680, 360448, 393216};
    int unit = i >> 15;
    int seg = segtab[unit];
    int li = i - segbase[seg];                    // group index within segment
    const float* src;
    switch (seg) {
        case 0: src = w0; break;
        case 1: src = w1; break;
        case 2: src = w2; break;
        case 3: src = w3; break;
        case 4: src = w4; break;
        case 5: src = w5; break;
        default: src = w6; break;
    }
    float4 a = *(const float4*)(src + (size_t)li * 8);
    float4 b = *(const float4*)(src + (size_t)li * 8 + 4);
    uint4 h, l;
    pack2(a.x, a.y, h.x, l.x);
    pack2(a.z, a.w, h.y, l.y);
    pack2(b.x, b.y, h.z, l.z);
    pack2(b.z, b.w, h.w, l.w);
    *(uint4*)(g_whi + (size_t)i * 4) = h;
    *(uint4*)(g_wlo + (size_t)i * 4) = l;
}

// ---------------- edge-index dtype detection ----------------
__global__ void detect_idx_kernel(const int* __restrict__ ei32) {
    if (threadIdx.x == 0 && blockIdx.x == 0) {
        int allzero = 1;
#pragma unroll
        for (int i = 1; i < 16; i += 2)
            if (ei32[i] != 0) allzero = 0;
        g_idx64_flag = allzero;
    }
}

// ---------------- scatter-add ----------------
__global__ void scatter_add_kernel(const void* __restrict__ ei) {
    int e = blockIdx.x;
    int dst;
    if (g_idx64_flag)
        dst = (int)((const long long*)ei)[E_N + e];
    else
        dst = ((const int*)ei)[E_N + e];
    if ((unsigned)dst >= (unsigned)E_N) return;
    const float* src = g_msg + (size_t)e * H_N;
    float* d = g_agg + (size_t)dst * H_N;
    for (int i = threadIdx.x; i < H_N; i += blockDim.x)
        atomicAdd(&d[i], src[i]);
}

// ---------------- GRU elementwise (+ h planes) ----------------
__global__ __launch_bounds__(256) void gru_kernel(const float* __restrict__ x) {
    int idx = blockIdx.x * 256 + threadIdx.x;
    if (idx >= E_N * 256) return;
    int e = idx >> 8, i = (idx & 255) << 1;
    const float* gi = g_gi + (size_t)e * H3_N;
    const float* gh = g_gh + (size_t)e * H3_N;
    float h2[2];
#pragma unroll
    for (int u = 0; u < 2; u++) {
        int c = i + u;
        float r = 1.f / (1.f + __expf(-(gi[c] + gh[c])));
        float z = 1.f / (1.f + __expf(-(gi[H_N + c] + gh[H_N + c])));
        float n = tanhf(gi[2 * H_N + c] + r * gh[2 * H_N + c]);
        h2[u] = (1.f - z) * n + z * x[(size_t)e * H_N + c];
        g_h[(size_t)e * H_N + c] = h2[u];
    }
    uint32_t h, l;
    pack2(h2[0], h2[1], h, l);
    g_hhi[idx] = h; g_hlo[idx] = l;
}

// ---------------- split Q/K per-head, 4 pairs/thread ----------------
__global__ __launch_bounds__(256) void split_qk_kernel() {
    int idx = blockIdx.x * 256 + threadIdx.x;   // < E_N * 64
    if (idx >= E_N * 64) return;
    int e = idx >> 6, hp = idx & 63;
    int head = hp >> 4, g = hp & 15;            // g: 4-pair group within head row
    const float scale = 0.08838834764831845f;
    size_t src = (size_t)e * H3_N + head * HD_N + (g << 3);
    float4 a = *(const float4*)&g_qkv[src];
    float4 b = *(const float4*)&g_qkv[src + 4];
    uint4 h, l;
    pack2(a.x * scale, a.y * scale, h.x, l.x);
    pack2(a.z * scale, a.w * scale, h.y, l.y);
    pack2(b.x * scale, b.y * scale, h.z, l.z);
    pack2(b.z * scale, b.w * scale, h.w, l.w);
    size_t dst = ((size_t)head * E_N + e) * 64 + (g << 2);
    *(uint4*)&g_qhi[dst] = h;
    *(uint4*)&g_qlo[dst] = l;
    a = *(const float4*)&g_qkv[src + H_N];
    b = *(const float4*)&g_qkv[src + H_N + 4];
    pack2(a.x, a.y, h.x, l.x);
    pack2(a.z, a.w, h.y, l.y);
    pack2(b.x, b.y, h.z, l.z);
    pack2(b.z, b.w, h.w, l.w);
    *(uint4*)&g_khi[dst] = h;
    *(uint4*)&g_klo[dst] = l;
}

// ---------------- tiled transposed V split (coalesced both sides) -------
// grid (2048/32, NH*HD/32), block 256; tile = 32 ep x 32 d
__global__ __launch_bounds__(256) void split_vt_kernel() {
    __shared__ uint32_t shi[32][33], slo[32][33];
    int bep = blockIdx.x << 5;
    int head = blockIdx.y >> 2;
    int d0 = (blockIdx.y & 3) << 5;
    int tx = threadIdx.x & 31;
    int ty = threadIdx.x >> 5;
#pragma unroll
    for (int i = 0; i < 4; i++) {
        int epl = (ty << 2) + i;
        int ep = bep + epl;
        int c = 2 * H_N + head * HD_N + d0 + tx;
        float v0 = g_qkv[(size_t)(2 * ep) * H3_N + c];
        float v1 = g_qkv[(size_t)(2 * ep + 1) * H3_N + c];
        uint32_t h, l;
        pack2(v0, v1, h, l);
        shi[tx][epl] = h;
        slo[tx][epl] = l;
    }
    __syncthreads();
#pragma unroll
    for (int i = 0; i < 4; i++) {
        int dl = (ty << 2) + i;
        size_t dst = ((size_t)head * HD_N + d0 + dl) * 2048 + bep + tx;
        g_vthi[dst] = shi[dl][tx];
        g_vtlo[dst] = slo[dl][tx];
    }
}

// ---------------- flash-attention, bf16x3 mma ----------------
#define AQ_STR 68
#define AK_STR 68
#define AV_STR 20
#define AS_STR 36
#define AT_QHI 0
#define AT_QLO (AT_QHI + 128 * AQ_STR)
#define AT_KHI (AT_QLO + 128 * AQ_STR)
#define AT_KLO (AT_KHI + 32 * AK_STR)
#define AT_VHI (AT_KLO + 32 * AK_STR)
#define AT_VLO (AT_VHI + 128 * AV_STR)
#define AT_SS  (AT_VLO + 128 * AV_STR)
#define AT_MS  (AT_SS + 128 * AS_STR)
#define AT_LS  (AT_MS + 128)
#define AT_AS  (AT_LS + 128)
#define AT_TOTAL (AT_AS + 128)
#define ATTN_SMEM_BYTES (AT_TOTAL * 4)

__global__ __launch_bounds__(256) void attn_bf16_kernel() {
    extern __shared__ uint32_t smw[];
    const uint32_t sb = smem_u32(smw);
    float* SS  = (float*)(smw + AT_SS);
    float* m_s = (float*)(smw + AT_MS);
    float* l_s = (float*)(smw + AT_LS);
    float* a_s = (float*)(smw + AT_AS);

    const int t = threadIdx.x;
    const int lane = t & 31;
    const int w = t >> 5;
    const int gid = lane >> 2;
    const int qid = lane & 3;
    const int r0 = (w << 4) + gid;
    const int q0 = blockIdx.x << 7;
    const int head = blockIdx.y;

    {
        size_t qb = ((size_t)head * E_N + q0) * 64;
        for (int i = t; i < 2048; i += 256) {
            int r = i >> 4, w4 = (i & 15) << 2;
            *(uint4*)(smw + AT_QHI + r * AQ_STR + w4) = *(const uint4*)&g_qhi[qb + r * 64 + w4];
            *(uint4*)(smw + AT_QLO + r * AQ_STR + w4) = *(const uint4*)&g_qlo[qb + r * 64 + w4];
        }
    }
    if (t < 128) { m_s[t] = -1e30f; l_s[t] = 0.f; }

    float o[16][4];
#pragma unroll
    for (int nf = 0; nf < 16; nf++)
#pragma unroll
        for (int c = 0; c < 4; c++) o[nf][c] = 0.f;

    __syncthreads();

    for (int j0 = 0; j0 < E_N; j0 += 32) {
        {
            size_t kb = ((size_t)head * E_N + j0) * 64;
            for (int i = t; i < 512; i += 256) {
                int r = i >> 4, w4 = (i & 15) << 2;
                *(uint4*)(smw + AT_KHI + r * AK_STR + w4) = *(const uint4*)&g_khi[kb + r * 64 + w4];
                *(uint4*)(smw + AT_KLO + r * AK_STR + w4) = *(const uint4*)&g_klo[kb + r * 64 + w4];
            }
            size_t vb = (size_t)head * HD_N * 2048 + (j0 >> 1);
            for (int i = t; i < 512; i += 256) {
                int r = i >> 2, w4 = (i & 3) << 2;
                *(uint4*)(smw + AT_VHI + r * AV_STR + w4) =
                    *(const uint4*)&g_vthi[vb + (size_t)r * 2048 + w4];
                *(uint4*)(smw + AT_VLO + r * AV_STR + w4) =
                    *(const uint4*)&g_vtlo[vb + (size_t)r * 2048 + w4];
            }
        }
        __syncthreads();

        float sacc[4][4];
#pragma unroll
        for (int nf = 0; nf < 4; nf++)
#pragma unroll
            for (int c = 0; c < 4; c++) sacc[nf][c] = 0.f;

#pragma unroll
        for (int ks = 0; ks < 8; ks++) {
            const int kw = ks << 3;
            uint32_t ahi[4], alo[4];
            uint32_t ao = (uint32_t)(((AT_QHI + ((w << 4) + (lane & 15)) * AQ_STR
                                       + kw + ((lane >> 4) << 2))) << 2);
            ldm_x4(ahi, sb + ao);
            ldm_x4(alo, sb + ao + (uint32_t)((AT_QLO - AT_QHI) << 2));
#pragma unroll
            for (int nf = 0; nf < 4; nf++) {
                uint32_t bo = (uint32_t)(((AT_KHI + ((nf << 3) + (lane & 7)) * AK_STR
                                           + kw + (((lane >> 3) & 1) << 2))) << 2);
                uint32_t bh[2], bl[2];
                ldm_x2(bh, sb + bo);
                ldm_x2(bl, sb + bo + (uint32_t)((AT_KLO - AT_KHI) << 2));
                mma_bf16(sacc[nf], ahi, bh);
                mma_bf16(sacc[nf], ahi, bl);
                mma_bf16(sacc[nf], alo, bh);
            }
        }
#pragma unroll
        for (int nf = 0; nf < 4; nf++) {
            int cb = (nf << 3) + (qid << 1);
            SS[r0 * AS_STR + cb]           = sacc[nf][0];
            SS[r0 * AS_STR + cb + 1]       = sacc[nf][1];
            SS[(r0 + 8) * AS_STR + cb]     = sacc[nf][2];
            SS[(r0 + 8) * AS_STR + cb + 1] = sacc[nf][3];
        }
        __syncthreads();

        {
            int r = t >> 1, cb = (t & 1) << 4;
            float* srow = &SS[r * AS_STR + cb];
            float mloc = -1e30f;
#pragma unroll
            for (int i = 0; i < 16; i++) mloc = fmaxf(mloc, srow[i]);
            mloc = fmaxf(mloc, __shfl_xor_sync(0xffffffffu, mloc, 1));
            float mold = m_s[r];
            float mnew = fmaxf(mold, mloc);
            float ssum = 0.f;
#pragma unroll
            for (int i = 0; i < 16; i++) {
                float p = __expf(srow[i] - mnew);
                srow[i] = p;
                ssum += p;
            }
            ssum += __shfl_xor_sync(0xffffffffu, ssum, 1);
            if (!(t & 1)) {
                float alpha = __expf(mold - mnew);
                m_s[r] = mnew;
                a_s[r] = alpha;
                l_s[r] = l_s[r] * alpha + ssum;
            }
        }
        __syncthreads();

        {
            float al0 = a_s[r0], al1 = a_s[r0 + 8];
#pragma unroll
            for (int nf = 0; nf < 16; nf++) {
                o[nf][0] *= al0; o[nf][1] *= al0;
                o[nf][2] *= al1; o[nf][3] *= al1;
            }
        }
#pragma unroll
        for (int ks = 0; ks < 2; ks++) {
            const int k0 = ks << 4;
            float p00 = SS[r0 * AS_STR + k0 + (qid << 1)];
            float p01 = SS[r0 * AS_STR + k0 + (qid << 1) + 1];
            float p10 = SS[(r0 + 8) * AS_STR + k0 + (qid << 1)];
            float p11 = SS[(r0 + 8) * AS_STR + k0 + (qid << 1) + 1];
            float p20 = SS[r0 * AS_STR + k0 + 8 + (qid << 1)];
            float p21 = SS[r0 * AS_STR + k0 + 8 + (qid << 1) + 1];
            float p30 = SS[(r0 + 8) * AS_STR + k0 + 8 + (qid << 1)];
            float p31 = SS[(r0 + 8) * AS_STR + k0 + 8 + (qid << 1) + 1];
            uint32_t phi[4], plo[4];
            pack2(p00, p01, phi[0], plo[0]);
            pack2(p10, p11, phi[1], plo[1]);
            pack2(p20, p21, phi[2], plo[2]);
            pack2(p30, p31, phi[3], plo[3]);
#pragma unroll
            for (int nf = 0; nf < 16; nf++) {
                uint32_t bo = (uint32_t)(((AT_VHI + ((nf << 3) + (lane & 7)) * AV_STR
                                           + (ks << 3) + (((lane >> 3) & 1) << 2))) << 2);
                uint32_t bh[2], bl[2];
                ldm_x2(bh, sb + bo);
                ldm_x2(bl, sb + bo + (uint32_t)((AT_VLO - AT_VHI) << 2));
                mma_bf16(o[nf], phi, bh);
                mma_bf16(o[nf], phi, bl);
                mma_bf16(o[nf], plo, bh);
            }
        }
        __syncthreads();
    }

    {
        float inv0 = 1.f / l_s[r0];
        float inv1 = 1.f / l_s[r0 + 8];
#pragma unroll
        for (int nf = 0; nf < 16; nf++) {
            int cw = head * 64 + (nf << 2) + qid;
            uint32_t h, l;
            pack2(o[nf][0] * inv0, o[nf][1] * inv0, h, l);
            g_attnhi[(size_t)(q0 + r0) * 256 + cw] = h;
            g_attnlo[(size_t)(q0 + r0) * 256 + cw] = l;
            pack2(o[nf][2] * inv1, o[nf][3] * inv1, h, l);
            g_attnhi[(size_t)(q0 + r0 + 8) * 256 + cw] = h;
            g_attnlo[(size_t)(q0 + r0 + 8) * 256 + cw] = l;
        }
    }
}

// ---------------- residual + LayerNorm (writes yn planes) ----------------
__global__ __launch_bounds__(256) void ln_kernel(const float* __restrict__ ln_g,
                                                 const float* __restrict__ ln_b) {
    __shared__ float reda[8], redb[8];
    int e = blockIdx.x;
    int t = threadIdx.x;
    const float* yp = g_yprj + (size_t)e * H_N;
    const float* hp = g_h + (size_t)e * H_N;
    int i0 = t << 1, i1 = i0 + 1;
    float v0 = yp[i0] + hp[i0];
    float v1 = yp[i1] + hp[i1];
    float s = v0 + v1, s2 = v0 * v0 + v1 * v1;
#pragma unroll
    for (int o = 16; o > 0; o >>= 1) {
        s  += __shfl_down_sync(0xffffffffu, s, o);
        s2 += __shfl_down_sync(0xffffffffu, s2, o);
    }
    int w = t >> 5;
    if ((t & 31) == 0) { reda[w] = s; redb[w] = s2; }
    __syncthreads();
    if (t < 8) {
        s = reda[t]; s2 = redb[t];
#pragma unroll
        for (int o = 4; o > 0; o >>= 1) {
            s  += __shfl_down_sync(0xffu, s, o);
            s2 += __shfl_down_sync(0xffu, s2, o);
        }
        if (t == 0) { reda[0] = s; redb[0] = s2; }
    }
    __syncthreads();
    float mu = reda[0] * (1.f / H_N);
    float var = redb[0] * (1.f / H_N) - mu * mu;
    float rstd = rsqrtf(var + 1e-5f);
    float y0 = (v0 - mu) * rstd * ln_g[i0] + ln_b[i0];
    float y1 = (v1 - mu) * rstd * ln_g[i1] + ln_b[i1];
    uint32_t h, l;
    pack2(y0, y1, h, l);
    g_ynhi[(size_t)e * 256 + t] = h;
    g_ynlo[(size_t)e * 256 + t] = l;
}

// ---------------- final dot ----------------
__global__ __launch_bounds__(256) void final_kernel(const float* __restrict__ W2,
                                                    const float* __restrict__ b2,
                                                    float* __restrict__ out) {
    __shared__ float red[8];
    int e = blockIdx.x;
    const float* fp = g_f + (size_t)e * FFN_N;
    float s = 0.f;
    for (int i = threadIdx.x; i < FFN_N; i += 256) s += fp[i] * W2[i];
#pragma unroll
    for (int o = 16; o > 0; o >>= 1) s += __shfl_down_sync(0xffffffffu, s, o);
    int w = threadIdx.x >> 5;
    if ((threadIdx.x & 31) == 0) red[w] = s;
    __syncthreads();
    if (threadIdx.x < 8) {
        s = red[threadIdx.x];
#pragma unroll
        for (int o = 4; o > 0; o >>= 1) s += __shfl_down_sync(0xffu, s, o);
        if (threadIdx.x == 0) out[e] = s + b2[0];
    }
}

// ---------------- launcher ----------------
extern "C" void kernel_launch(void* const* d_in, const int* in_sizes, int n_in,
                              void* d_out, int out_size) {
    const float* x       = (const float*)d_in[0];
    const void*  ei      = d_in[1];
    const float* W_msg   = (const float*)d_in[2];
    const float* b_msg   = (const float*)d_in[3];
    const float* W_ih    = (const float*)d_in[4];
    const float* b_ih    = (const float*)d_in[5];
    const float* W_hh    = (const float*)d_in[6];
    const float* b_hh    = (const float*)d_in[7];
    const float* W_inp   = (const float*)d_in[8];
    const float* b_inp   = (const float*)d_in[9];
    const float* W_outp  = (const float*)d_in[10];
    const float* b_outp  = (const float*)d_in[11];
    const float* ln_g    = (const float*)d_in[12];
    const float* ln_b    = (const float*)d_in[13];
    const float* W_lin   = (const float*)d_in[14];
    const float* b_lin   = (const float*)d_in[15];
    const float* W_f1    = (const float*)d_in[16];
    const float* b_f1    = (const float*)d_in[17];
    const float* W_f2    = (const float*)d_in[18];
    const float* b_f2    = (const float*)d_in[19];
    float* out = (float*)d_out;

    float *p_msg, *p_agg, *p_gi, *p_gh, *p_qkv, *p_yprj, *p_f;
    cudaGetSymbolAddress((void**)&p_msg,  g_msg);
    cudaGetSymbolAddress((void**)&p_agg,  g_agg);
    cudaGetSymbolAddress((void**)&p_gi,   g_gi);
    cudaGetSymbolAddress((void**)&p_gh,   g_gh);
    cudaGetSymbolAddress((void**)&p_qkv,  g_qkv);
    cudaGetSymbolAddress((void**)&p_yprj, g_yprj);
    cudaGetSymbolAddress((void**)&p_f,    g_f);
    uint32_t *p_xhi, *p_xlo, *p_agghi, *p_agglo, *p_hhi, *p_hlo;
    uint32_t *p_attnhi, *p_attnlo, *p_ynhi, *p_ynlo, *p_gacthi, *p_gactlo;
    uint32_t *p_whi, *p_wlo;
    cudaGetSymbolAddress((void**)&p_xhi,    g_xhi);
    cudaGetSymbolAddress((void**)&p_xlo,    g_xlo);
    cudaGetSymbolAddress((void**)&p_agghi,  g_agghi);
    cudaGetSymbolAddress((void**)&p_agglo,  g_agglo);
    cudaGetSymbolAddress((void**)&p_hhi,    g_hhi);
    cudaGetSymbolAddress((void**)&p_hlo,    g_hlo);
    cudaGetSymbolAddress((void**)&p_attnhi, g_attnhi);
    cudaGetSymbolAddress((void**)&p_attnlo, g_attnlo);
    cudaGetSymbolAddress((void**)&p_ynhi,   g_ynhi);
    cudaGetSymbolAddress((void**)&p_ynlo,   g_ynlo);
    cudaGetSymbolAddress((void**)&p_gacthi, g_gacthi);
    cudaGetSymbolAddress((void**)&p_gactlo, g_gactlo);
    cudaGetSymbolAddress((void**)&p_whi,    g_whi);
    cudaGetSymbolAddress((void**)&p_wlo,    g_wlo);

    cudaFuncSetAttribute(gemm_pk<0>, cudaFuncAttributeMaxDynamicSharedMemorySize, GEMM_SMEM_BYTES);
    cudaFuncSetAttribute(gemm_pk<1>, cudaFuncAttributeMaxDynamicSharedMemorySize, GEMM_SMEM_BYTES);
    cudaFuncSetAttribute(gemm_pk<2>, cudaFuncAttributeMaxDynamicSharedMemorySize, GEMM_SMEM_BYTES);
    cudaFuncSetAttribute(attn_bf16_kernel, cudaFuncAttributeMaxDynamicSharedMemorySize, ATTN_SMEM_BYTES);

    // launch order: slot 3 (0-based) = the big gh GEMM, for ncu capture
    // 0) x planes
    split_pairs_v4<<<(E_N * 64) / 256, 256>>>(x, p_xhi, p_xlo, E_N * 64);
    // 1) weights
    split_weights_kernel<<<(WTOTAL / 4 + 255) / 256, 256>>>(W_msg, W_ih, W_hh, W_inp, W_outp, W_lin, W_f1);
    // 2) detect edge_index dtype
    detect_idx_kernel<<<1, 32>>>((const int*)ei);
    // 3) gh = x @ W_hh^T + b_hh   <-- profiled launch
    gemm_pk<0><<<dim3(H3_N / 128, 32), 256, GEMM_SMEM_BYTES>>>(
        p_xhi, p_xlo, p_whi + WOFF_HH, p_wlo + WOFF_HH, b_hh, p_gh, nullptr, nullptr, H3_N, H_N);
    // 4) zero agg
    zero_kernel<<<(E_N * H_N + 255) / 256, 256>>>(p_agg, E_N * H_N);
    // 5) msg = relu(x @ W_msg^T + b)
    gemm_pk<1><<<dim3(H_N / 128, 32), 256, GEMM_SMEM_BYTES>>>(
        p_xhi, p_xlo, p_whi + WOFF_MSG, p_wlo + WOFF_MSG, b_msg, p_msg, nullptr, nullptr, H_N, H_N);
    // 6) scatter-add
    scatter_add_kernel<<<E_N, 128>>>(ei);
    // 7) agg planes
    split_pairs_v4<<<(E_N * 64) / 256, 256>>>(p_agg, p_agghi, p_agglo, E_N * 64);
    // 8) gi
    gemm_pk<0><<<dim3(H3_N / 128, 32), 256, GEMM_SMEM_BYTES>>>(
        p_agghi, p_agglo, p_whi + WOFF_IH, p_wlo + WOFF_IH, b_ih, p_gi, nullptr, nullptr, H3_N, H_N);
    // 9) GRU
    gru_kernel<<<(E_N * 256) / 256, 256>>>(x);
    // 10) qkv
    gemm_pk<0><<<dim3(H3_N / 128, 32), 256, GEMM_SMEM_BYTES>>>(
        p_hhi, p_hlo, p_whi + WOFF_INP, p_wlo + WOFF_INP, b_inp, p_qkv, nullptr, nullptr, H3_N, H_N);
    // 11-13) splits + attention
    split_qk_kernel<<<(E_N * 64) / 256, 256>>>();
    split_vt_kernel<<<dim3(64, 16), 256>>>();
    attn_bf16_kernel<<<dim3(E_N / 128, NH_N), 256, ATTN_SMEM_BYTES>>>();
    // 14) out-proj
    gemm_pk<0><<<dim3(H_N / 128, 32), 256, GEMM_SMEM_BYTES>>>(
        p_attnhi, p_attnlo, p_whi + WOFF_OUTP, p_wlo + WOFF_OUTP, b_outp, p_yprj, nullptr, nullptr, H_N, H_N);
    // 15) residual + LN
    ln_kernel<<<E_N, 256>>>(ln_g, ln_b);
    // 16) g = relu(yn @ W_lin^T + b) -> packed
    gemm_pk<2><<<dim3(H_N / 128, 32), 256, GEMM_SMEM_BYTES>>>(
        p_ynhi, p_ynlo, p_whi + WOFF_LIN, p_wlo + WOFF_LIN, b_lin, nullptr, p_gacthi, p_gactlo, H_N, H_N);
    // 17) f = relu(g @ W_f1^T + b_f1)
    gemm_pk<1><<<dim3(FFN_N / 128, 32), 256, GEMM_SMEM_BYTES>>>(
        p_gacthi, p_gactlo, p_whi + WOFF_F1, p_wlo + WOFF_F1, b_f1, p_f, nullptr, nullptr, FFN_N, H_N);
    // 18) out
    final_kernel<<<E_N, 256>>>(W_f2, b_f2, out);
}